// round 16
// baseline (speedup 1.0000x reference)
#include <cuda_runtime.h>

// Cosine similarity per row: a,b [16,4096,256] f32 -> out [16,4096] f32.
// out[r] = dot(a_r,b_r) * rsqrt(max(|a_r|^2,EPS)) * rsqrt(max(|b_r|^2,EPS))
//
// Persistent warp-per-row at FULL occupancy. R7's persistent variant lost
// because its manual prefetch cost 52 regs -> occ 4. Here the body is the
// 256-bit-load version (29 regs, occ 8) and the pipelining comes free: the
// next iteration's 2 LDG.256 depend only on the A/B registers, which are
// released by the FMA tree -- so the HW overlaps them with the current
// row's shuffle butterfly. No wave transitions, no last-wave tail.

#define EPSV 1e-12f

struct F8 { float4 lo, hi; };

__device__ __forceinline__ F8 ldg256(const float* p)
{
    F8 v;
    asm("ld.global.nc.v8.b32 {%0,%1,%2,%3,%4,%5,%6,%7}, [%8];"
        : "=f"(v.lo.x), "=f"(v.lo.y), "=f"(v.lo.z), "=f"(v.lo.w),
          "=f"(v.hi.x), "=f"(v.hi.y), "=f"(v.hi.z), "=f"(v.hi.w)
        : "l"(p));
    return v;
}

__global__ __launch_bounds__(256, 8)
void cosine_rows_w256_pers(const float* __restrict__ a,
                           const float* __restrict__ b,
                           float* __restrict__ out,
                           int n_rows)
{
    const int lane   = threadIdx.x & 31;
    const int gwarp  = (blockIdx.x * blockDim.x + threadIdx.x) >> 5;
    const int nwarps = (gridDim.x * blockDim.x) >> 5;

    for (int row = gwarp; row < n_rows; row += nwarps) {
        // Row = 256 floats; lane covers floats [lane*8, lane*8+8).
        const long base = (long)row * 256 + lane * 8;

        F8 A = ldg256(a + base);
        F8 B = ldg256(b + base);

        float d0 = A.lo.x*B.lo.x + A.lo.y*B.lo.y + A.lo.z*B.lo.z + A.lo.w*B.lo.w;
        float d1 = A.hi.x*B.hi.x + A.hi.y*B.hi.y + A.hi.z*B.hi.z + A.hi.w*B.hi.w;
        float s0 = A.lo.x*A.lo.x + A.lo.y*A.lo.y + A.lo.z*A.lo.z + A.lo.w*A.lo.w;
        float s1 = A.hi.x*A.hi.x + A.hi.y*A.hi.y + A.hi.z*A.hi.z + A.hi.w*A.hi.w;
        float t0 = B.lo.x*B.lo.x + B.lo.y*B.lo.y + B.lo.z*B.lo.z + B.lo.w*B.lo.w;
        float t1 = B.hi.x*B.hi.x + B.hi.y*B.hi.y + B.hi.z*B.hi.z + B.hi.w*B.hi.w;

        float dot = d0 + d1;
        float sa  = s0 + s1;
        float sb  = t0 + t1;

        // 5-stage warp butterfly; next iteration's loads overlap this chain.
        #pragma unroll
        for (int off = 16; off > 0; off >>= 1) {
            dot += __shfl_xor_sync(0xFFFFFFFFu, dot, off);
            sa  += __shfl_xor_sync(0xFFFFFFFFu, sa,  off);
            sb  += __shfl_xor_sync(0xFFFFFFFFu, sb,  off);
        }

        if (lane == 0) {
            float inv = rsqrtf(fmaxf(sa, EPSV)) * rsqrtf(fmaxf(sb, EPSV));
            out[row] = dot * inv;
        }
    }
}

extern "C" void kernel_launch(void* const* d_in, const int* in_sizes, int n_in,
                              void* d_out, int out_size)
{
    const float* a = (const float*)d_in[0];
    const float* b = (const float*)d_in[1];
    float* out = (float*)d_out;

    const int n_rows = out_size;     // 16*4096 = 65536

    // Persistent single wave: 152 SMs x 8 CTAs x 256 threads = 9728 warps,
    // ~6.7 rows per warp via grid-stride.
    const int blocks = 152 * 8;

    cosine_rows_w256_pers<<<blocks, 256>>>(a, b, out, n_rows);
}

// round 17
// speedup vs baseline: 1.0038x; 1.0038x over previous
#include <cuda_runtime.h>

// Cosine similarity per row: a,b [16,4096,256] f32 -> out [16,4096] f32.
// out[r] = dot(a_r,b_r) * rsqrt(max(|a_r|^2,EPS)) * rsqrt(max(|b_r|^2,EPS))
//
// Waved launch (persistent loses: CTA replacement is the prefetcher).
// 2 rows per warp, all 4 LDG.256 front-batched (4KB in flight per warp).
// Merged reduction: one xor-16 stage combines cross-half partials for BOTH
// rows (6 SHFL), then each 16-lane half selects its row and finishes with a
// 4-stage butterfly (12 SHFL). 18 SHFL / 2 rows vs 30 for two full
// butterflies. Lane 0 writes row0, lane 16 writes row1.

#define EPSV 1e-12f

struct F8 { float4 lo, hi; };

__device__ __forceinline__ F8 ldg256(const float* p)
{
    F8 v;
    asm("ld.global.nc.v8.b32 {%0,%1,%2,%3,%4,%5,%6,%7}, [%8];"
        : "=f"(v.lo.x), "=f"(v.lo.y), "=f"(v.lo.z), "=f"(v.lo.w),
          "=f"(v.hi.x), "=f"(v.hi.y), "=f"(v.hi.z), "=f"(v.hi.w)
        : "l"(p));
    return v;
}

__device__ __forceinline__ void sums8(const F8& A, const F8& B,
                                      float& dot, float& sa, float& sb)
{
    float d0 = A.lo.x*B.lo.x + A.lo.y*B.lo.y + A.lo.z*B.lo.z + A.lo.w*B.lo.w;
    float d1 = A.hi.x*B.hi.x + A.hi.y*B.hi.y + A.hi.z*B.hi.z + A.hi.w*B.hi.w;
    float s0 = A.lo.x*A.lo.x + A.lo.y*A.lo.y + A.lo.z*A.lo.z + A.lo.w*A.lo.w;
    float s1 = A.hi.x*A.hi.x + A.hi.y*A.hi.y + A.hi.z*A.hi.z + A.hi.w*A.hi.w;
    float t0 = B.lo.x*B.lo.x + B.lo.y*B.lo.y + B.lo.z*B.lo.z + B.lo.w*B.lo.w;
    float t1 = B.hi.x*B.hi.x + B.hi.y*B.hi.y + B.hi.z*B.hi.z + B.hi.w*B.hi.w;
    dot = d0 + d1;
    sa  = s0 + s1;
    sb  = t0 + t1;
}

__global__ __launch_bounds__(256, 6)
void cosine_rows_w256x2(const float* __restrict__ a,
                        const float* __restrict__ b,
                        float* __restrict__ out,
                        int n_rows)
{
    const int lane = threadIdx.x & 31;
    const int warp = threadIdx.x >> 5;

    const int row0 = blockIdx.x * 16 + warp * 2;   // this warp: row0, row0+1
    if (row0 >= n_rows) return;

    const long base0 = (long)row0 * 256 + lane * 8;
    const long base1 = base0 + 256;

    // 4 front-batched LDG.256 (4KB in flight per warp).
    F8 A0 = ldg256(a + base0);
    F8 B0 = ldg256(b + base0);
    F8 A1 = ldg256(a + base1);
    F8 B1 = ldg256(b + base1);

    float dot0, sa0, sb0, dot1, sa1, sb1;
    sums8(A0, B0, dot0, sa0, sb0);
    sums8(A1, B1, dot1, sa1, sb1);

    // Stage 1: xor-16 on all six partials (cross-half combine for both rows).
    dot0 += __shfl_xor_sync(0xFFFFFFFFu, dot0, 16);
    sa0  += __shfl_xor_sync(0xFFFFFFFFu, sa0,  16);
    sb0  += __shfl_xor_sync(0xFFFFFFFFu, sb0,  16);
    dot1 += __shfl_xor_sync(0xFFFFFFFFu, dot1, 16);
    sa1  += __shfl_xor_sync(0xFFFFFFFFu, sa1,  16);
    sb1  += __shfl_xor_sync(0xFFFFFFFFu, sb1,  16);

    // Each half-warp finishes its own row: lower half row0, upper half row1.
    const bool lowhalf = (lane < 16);
    float dot = lowhalf ? dot0 : dot1;
    float sa  = lowhalf ? sa0  : sa1;
    float sb  = lowhalf ? sb0  : sb1;

    #pragma unroll
    for (int off = 8; off > 0; off >>= 1) {
        dot += __shfl_xor_sync(0xFFFFFFFFu, dot, off);
        sa  += __shfl_xor_sync(0xFFFFFFFFu, sa,  off);
        sb  += __shfl_xor_sync(0xFFFFFFFFu, sb,  off);
    }

    if ((lane & 15) == 0) {
        const int row = row0 + (lane >> 4);
        if (row < n_rows) {
            float inv = rsqrtf(fmaxf(sa, EPSV)) * rsqrtf(fmaxf(sb, EPSV));
            out[row] = dot * inv;
        }
    }
}

extern "C" void kernel_launch(void* const* d_in, const int* in_sizes, int n_in,
                              void* d_out, int out_size)
{
    const float* a = (const float*)d_in[0];
    const float* b = (const float*)d_in[1];
    float* out = (float*)d_out;

    const int n_rows = out_size;               // 65536
    const int blocks = (n_rows + 15) / 16;     // 16 rows per 256-thread block

    cosine_rows_w256x2<<<blocks, 256>>>(a, b, out, n_rows);
}